// round 7
// baseline (speedup 1.0000x reference)
#include <cuda_runtime.h>
#include <cstddef>

#define Bb 8
#define Tt 2048
#define Dd 512
#define Hh 512
#define FOURH 2048
#define GRID_R 128

typedef unsigned long long u64;

// ---------------- scratch (static device globals: allocation-free) ----------------
__device__ float g_wx[(size_t)Bb * Tt * FOURH];   // 128 MiB: precomputed x @ W^T + b
__device__ float g_h[2][Bb * Hh];                 // double-buffered hidden state
__device__ unsigned g_cnt[4 * 32];                // 4 arrival counters, 128B apart

// ---------------- packed f32x2 helpers (b64 regs via "l" constraint) ----------------
__device__ __forceinline__ void fma2(u64 &acc, u64 a, u64 b) {
    asm("fma.rn.f32x2 %0, %1, %2, %0;" : "+l"(acc) : "l"(a), "l"(b));
}
__device__ __forceinline__ u64 dup2(float s) {
    u64 d; asm("mov.b64 %0, {%1, %1};" : "=l"(d) : "f"(s)); return d;
}
__device__ __forceinline__ void unpack2(u64 v, float &lo, float &hi) {
    asm("mov.b64 {%0, %1}, %2;" : "=f"(lo), "=f"(hi) : "l"(v));
}

// ---------------- scoped sync primitives ----------------
__device__ __forceinline__ void cnt_arrive_release(unsigned* p) {
    asm volatile("red.release.gpu.global.add.u32 [%0], %1;"
                 :: "l"(p), "r"(1u) : "memory");
}
__device__ __forceinline__ unsigned ld_acquire(const unsigned* p) {
    unsigned v;
    asm volatile("ld.acquire.gpu.global.u32 %0, [%1];"
                 : "=r"(v) : "l"(p) : "memory");
    return v;
}
__device__ __forceinline__ void fence_acq() {
    asm volatile("fence.acq_rel.gpu;" ::: "memory");  // flushes stale L1 (CCTL.IVALL)
}

// ---------------- fast gate math (MUFU-based, ~1e-7 rel err) ----------------
__device__ __forceinline__ float sigm_f(float x) {
    return __fdividef(1.f, 1.f + __expf(-x));
}
__device__ __forceinline__ float tanh_f(float x) {
    float e = __expf(2.f * x);
    return 1.f - __fdividef(2.f, e + 1.f);
}

// =====================================================================
// Kernel 1: Wx = x[16384,512] @ W_w[2048,512]^T + W_b  -> g_wx[16384,2048]
// (unchanged from R6; ~60% of fp32x2 roofline)
// =====================================================================
__global__ void __launch_bounds__(256) gemm_wx_kernel(
    const float* __restrict__ x, const float* __restrict__ Ww,
    const float* __restrict__ Wb)
{
    __shared__ __align__(16) float a_s[32][132];
    __shared__ __align__(16) float b_s[32][132];

    const int tid = threadIdx.x;
    const int tx = tid & 15, ty = tid >> 4;
    const int m0 = blockIdx.y * 128, n0 = blockIdx.x * 128;

    u64 acc[8][4];
    #pragma unroll
    for (int i = 0; i < 8; i++)
        #pragma unroll
        for (int j = 0; j < 4; j++) acc[i][j] = 0ull;

    const int lr = tid >> 3;
    const int kq = (tid & 7) * 4;

    for (int kc = 0; kc < 512; kc += 32) {
        __syncthreads();
        #pragma unroll
        for (int i = 0; i < 4; i++) {
            int r = lr + 32 * i;
            float4 av = *(const float4*)&x[(size_t)(m0 + r) * 512 + kc + kq];
            a_s[kq + 0][r] = av.x; a_s[kq + 1][r] = av.y;
            a_s[kq + 2][r] = av.z; a_s[kq + 3][r] = av.w;
            float4 bv = *(const float4*)&Ww[(size_t)(n0 + r) * 512 + kc + kq];
            b_s[kq + 0][r] = bv.x; b_s[kq + 1][r] = bv.y;
            b_s[kq + 2][r] = bv.z; b_s[kq + 3][r] = bv.w;
        }
        __syncthreads();
        #pragma unroll
        for (int k = 0; k < 32; k++) {
            float4 af0 = *(const float4*)&a_s[k][ty * 8];
            float4 af1 = *(const float4*)&a_s[k][ty * 8 + 4];
            ulonglong2 b01 = *(const ulonglong2*)&b_s[k][tx * 8];
            ulonglong2 b23 = *(const ulonglong2*)&b_s[k][tx * 8 + 4];
            u64 ad[8];
            ad[0] = dup2(af0.x); ad[1] = dup2(af0.y); ad[2] = dup2(af0.z); ad[3] = dup2(af0.w);
            ad[4] = dup2(af1.x); ad[5] = dup2(af1.y); ad[6] = dup2(af1.z); ad[7] = dup2(af1.w);
            #pragma unroll
            for (int i = 0; i < 8; i++) {
                fma2(acc[i][0], ad[i], b01.x);
                fma2(acc[i][1], ad[i], b01.y);
                fma2(acc[i][2], ad[i], b23.x);
                fma2(acc[i][3], ad[i], b23.y);
            }
        }
    }

    float wb[8];
    #pragma unroll
    for (int j = 0; j < 8; j++) wb[j] = Wb[n0 + tx * 8 + j];

    #pragma unroll
    for (int i = 0; i < 8; i++) {
        float o[8];
        #pragma unroll
        for (int jp = 0; jp < 4; jp++) {
            float lo, hi; unpack2(acc[i][jp], lo, hi);
            o[jp * 2]     = lo + wb[jp * 2];
            o[jp * 2 + 1] = hi + wb[jp * 2 + 1];
        }
        size_t row = (size_t)(m0 + ty * 8 + i);
        float4* dst = (float4*)&g_wx[row * FOURH + n0 + tx * 8];
        dst[0] = make_float4(o[0], o[1], o[2], o[3]);
        dst[1] = make_float4(o[4], o[5], o[6], o[7]);
    }
}

// =====================================================================
// Kernel 2: persistent recurrent sLSTM. 128 blocks x 512 threads (16 warps).
// Block owns hidden units [4*blk, 4*blk+4).
// Warp w: unit ju = w>>2, batch-pair bp = w&3 -> computes ALL 4 gates for
// (unit j0+ju, batches 2bp..2bp+1), finalizes and stores h itself.
// Step: poll(4 counters) -> fence -> sync -> L1-cached h loads -> 64 fma2
//       -> 9-shfl butterfly -> parallel activations -> 3-shfl gather
//       -> c-update/store (lanes 0,16) -> sync -> tid0 RED arrive.
// =====================================================================
__global__ void __launch_bounds__(512) lstm_rec_kernel(
    const float* __restrict__ Uw, const float* __restrict__ Ub,
    const float* __restrict__ alpha, float* __restrict__ out)
{
    const int tid  = threadIdx.x;
    const int w    = tid >> 5;
    const int lane = tid & 31;
    const int ju   = w >> 2;       // local hidden unit 0..3
    const int bp   = w & 3;        // batch pair (batches 2bp, 2bp+1)
    const int blk  = blockIdx.x;
    const int j0   = blk * 4;
    const int jg   = j0 + ju;      // global hidden unit for this warp

    // lane's (gate, batch) slot: m = (lane>>2)&7, g = m&3, bi = m>>2
    const int m  = (lane >> 2) & 7;
    const int g  = m & 3;
    const int bi = m >> 2;
    const int b  = 2 * bp + bi;    // batch 0..7 for this lane's slot

    // U_w rows register-resident: warp holds rows (g, jg) for g=0..3;
    // lane owns cols {4*lane + 128*q : q=0..3}.
    ulonglong2 u[4][4];
    #pragma unroll
    for (int gg = 0; gg < 4; gg++)
        #pragma unroll
        for (int q = 0; q < 4; q++)
            u[gg][q] = *(const ulonglong2*)&Uw[(size_t)(gg * Hh + jg) * Hh + 128 * q + 4 * lane];

    const float ub_r    = Ub[g * Hh + jg];   // per-lane (its gate)
    const float alpha_r = alpha[jg];
    float c_st = 0.f;                         // live in lanes 0 and 16 only

    // publish h0 = 0 (warp 0 zeroes this block's 32-float share of g_h[0])
    if (w == 0) {
        g_h[0][blk * 32 + lane] = 0.f;
        __syncwarp();
        if (lane == 0) cnt_arrive_release(&g_cnt[(blk & 3) * 32]);
    }
    __syncthreads();

    for (int t = 0; t < Tt; ++t) {
        // prefetch Wx_t for this lane's (g, b) slot (independent of h)
        const float wx = __ldg(&g_wx[((size_t)b * Tt + t) * FOURH + g * Hh + jg]);

        // ---- barrier: all 128 blocks published h_t (4 counters, lanes 0-3 poll)
        if (w == 0) {
            const unsigned tgt = 32u * (unsigned)(t + 1);
            int spins = 0;
            for (;;) {
                unsigned cv = (lane < 4) ? ld_acquire(&g_cnt[lane * 32]) : tgt;
                if (__all_sync(0xffffffffu, cv >= tgt)) break;
                if (++spins > 64) __nanosleep(64);
            }
            if (lane == 0) fence_acq();   // CCTL.IVALL: drop stale L1 h lines
        }
        __syncthreads();

        // ---- dots: 4 gates x 2 batches over full 512 cols.
        // Normal (L1-cached) loads: 4 warps per SMSP share the same 2 h rows.
        const float* hbuf = g_h[t & 1];
        u64 acc[4][2];
        #pragma unroll
        for (int gg = 0; gg < 4; gg++) { acc[gg][0] = 0ull; acc[gg][1] = 0ull; }
        #pragma unroll
        for (int bb2 = 0; bb2 < 2; bb2++) {
            ulonglong2 h2[4];
            #pragma unroll
            for (int q = 0; q < 4; q++)
                h2[q] = *(const ulonglong2*)&hbuf[(2 * bp + bb2) * Hh + 128 * q + 4 * lane];
            #pragma unroll
            for (int q = 0; q < 4; q++)
                #pragma unroll
                for (int gg = 0; gg < 4; gg++) {
                    fma2(acc[gg][bb2], u[gg][q].x, h2[q].x);
                    fma2(acc[gg][bb2], u[gg][q].y, h2[q].y);
                }
        }

        // collapse pair halves -> v[mm], mm = gate + 4*batchhalf
        float v[8];
        #pragma unroll
        for (int gg = 0; gg < 4; gg++)
            #pragma unroll
            for (int bb2 = 0; bb2 < 2; bb2++) {
                float lo, hi; unpack2(acc[gg][bb2], lo, hi);
                v[gg + 4 * bb2] = lo + hi;
            }

        // 9-shfl butterfly: lane L ends with total for mm=(L>>2)&7
        {
            const bool up16 = (lane & 16) != 0;
            #pragma unroll
            for (int i = 0; i < 4; i++) {
                float a = v[i], bv = v[i + 4];
                float mine = up16 ? bv : a, oth = up16 ? a : bv;
                v[i] = mine + __shfl_xor_sync(0xffffffffu, oth, 16);
            }
            const bool up8 = (lane & 8) != 0;
            #pragma unroll
            for (int i = 0; i < 2; i++) {
                float a = v[i], bv = v[i + 2];
                float mine = up8 ? bv : a, oth = up8 ? a : bv;
                v[i] = mine + __shfl_xor_sync(0xffffffffu, oth, 8);
            }
            const bool up4 = (lane & 4) != 0;
            {
                float a = v[0], bv = v[1];
                float mine = up4 ? bv : a, oth = up4 ? a : bv;
                v[0] = mine + __shfl_xor_sync(0xffffffffu, oth, 4);
            }
            v[0] += __shfl_xor_sync(0xffffffffu, v[0], 2);
            v[0] += __shfl_xor_sync(0xffffffffu, v[0], 1);
        }

        // parallel activations: every lane activates its own slot
        const float z = v[0] + wx + ub_r;
        const float a = (g == 3) ? tanh_f(z) : sigm_f(z);

        // gather i/f/o/g at lanes 0 (bi=0) and 16 (bi=1); update c; store h
        const float a_f = __shfl_down_sync(0xffffffffu, a, 4);
        const float a_o = __shfl_down_sync(0xffffffffu, a, 8);
        const float a_g = __shfl_down_sync(0xffffffffu, a, 12);
        if ((lane & 15) == 0) {
            c_st = alpha_r * (a_f * c_st + a * a_g);
            const float hv = a_o * tanh_f(c_st);
            g_h[(t + 1) & 1][b * Hh + jg] = hv;
            out[((size_t)b * Tt + t) * Hh + jg] = hv;
            if (t == Tt - 1) {
                out[(size_t)Bb * Tt * Hh + b * Hh + jg] = hv;                       // final h
                out[(size_t)Bb * Tt * Hh + (size_t)Bb * Hh + b * Hh + jg] = c_st;   // final c
            }
        }

        // ---- arrive: block's stores done -> one release-RED per block
        __syncthreads();
        if (tid == 0) cnt_arrive_release(&g_cnt[(blk & 3) * 32]);
    }

    // block 0 resets counters once every arrival has landed (graph-replay safe)
    if (blk == 0 && w == 0 && lane < 4) {
        const unsigned fin = 32u * (unsigned)(Tt + 1);
        int spins = 0;
        while (ld_acquire(&g_cnt[lane * 32]) < fin) {
            if (++spins > 64) __nanosleep(128);
        }
        g_cnt[lane * 32] = 0u;
    }
}

// =====================================================================
extern "C" void kernel_launch(void* const* d_in, const int* in_sizes, int n_in,
                              void* d_out, int out_size)
{
    const float* x     = (const float*)d_in[0];
    const float* Ww    = (const float*)d_in[1];
    const float* Wb    = (const float*)d_in[2];
    const float* Uw    = (const float*)d_in[3];
    const float* Ub    = (const float*)d_in[4];
    const float* alpha = (const float*)d_in[5];
    float* out = (float*)d_out;

    dim3 ggrid(FOURH / 128, (Bb * Tt) / 128);   // 16 x 128
    gemm_wx_kernel<<<ggrid, 256>>>(x, Ww, Wb);
    lstm_rec_kernel<<<GRID_R, 512>>>(Uw, Ub, alpha, out);
}